// round 8
// baseline (speedup 1.0000x reference)
#include <cuda_runtime.h>
#include <math.h>
#include <stdint.h>

#define BATCH 4096
#define HLEN  200
#define XD    384
#define H1    200
#define N1P   256     // W1 rows padded
#define H2    80
#define BN_EPS 1e-5f
#define RPB   8       // rows per embed CTA

// ---------------- device scratch (static allocation only) ----------------
__device__ __align__(16) uint2 g_xa[BATCH * XD];   // tf32 (hi,lo) of raw x
__device__ __align__(16) uint2 g_w1[N1P * XD];     // tf32 (hi,lo) of scale∘W1, zero-padded
__device__ float g_c[N1P];                         // sum_k shift[k]*W1[n,k] + b1[n]
__device__ float g_y1[BATCH * H1];
__device__ float g_sum[XD];                        // zeroed; finalize resets after use
__device__ float g_sumsq[XD];
__device__ float g_scale[XD];
__device__ float g_shift[XD];
__device__ int   g_first_inactive = BATCH;         // finalize resets after use

// ---------------- helpers ----------------
__device__ __forceinline__ uint32_t f2tf32(float f) {
    uint32_t r;
    asm("cvt.rna.tf32.f32 %0, %1;" : "=r"(r) : "f"(f));
    return r;
}
__device__ __forceinline__ uint2 tf32_split(float f) {
    uint32_t hi = f2tf32(f);
    float lo = f - __uint_as_float(hi);
    return make_uint2(hi, f2tf32(lo));
}
__device__ __forceinline__ void store_split4(uint2* dst, float4 v) {
    uint2 s0 = tf32_split(v.x), s1 = tf32_split(v.y);
    uint2 s2 = tf32_split(v.z), s3 = tf32_split(v.w);
    *(uint4*)(dst)     = make_uint4(s0.x, s0.y, s1.x, s1.y);
    *(uint4*)(dst + 2) = make_uint4(s2.x, s2.y, s3.x, s3.y);
}
__device__ __forceinline__ void mma_tf32(float4& d,
                                         uint32_t a0, uint32_t a1,
                                         uint32_t a2, uint32_t a3,
                                         uint32_t b0, uint32_t b1) {
    asm volatile(
        "mma.sync.aligned.m16n8k8.row.col.f32.tf32.tf32.f32 "
        "{%0,%1,%2,%3}, {%4,%5,%6,%7}, {%8,%9}, {%0,%1,%2,%3};"
        : "+f"(d.x), "+f"(d.y), "+f"(d.z), "+f"(d.w)
        : "r"(a0), "r"(a1), "r"(a2), "r"(a3), "r"(b0), "r"(b1));
}

// ---------------- kernels ----------------

// outer-break semantics: first row b with history[b,0]==0 deactivates rows >= b
__global__ void scan_kernel(const int* __restrict__ history) {
    int b = blockIdx.x * blockDim.x + threadIdx.x;
    if (b < BATCH && history[b * HLEN] == 0) atomicMin(&g_first_inactive, b);
}

// warp-per-row embedding gather + pool; writes tf32-split x; fused BN sums.
__global__ void embed_kernel(const int* __restrict__ user,
                             const int* __restrict__ item,
                             const int* __restrict__ history,
                             const int* __restrict__ cate_list,
                             const float* __restrict__ uW,   // [100000,128]
                             const float* __restrict__ iW,   // [100000,64]
                             const float* __restrict__ cW) { // [1000,64]
    __shared__ int   ids[RPB][HLEN];
    __shared__ float sx[RPB][XD];     // per-row x values for BN reduction

    int b0  = blockIdx.x * RPB;
    int tid = threadIdx.x;

    for (int i = tid; i < RPB * HLEN; i += 256)
        ids[i / HLEN][i % HLEN] = history[b0 * HLEN + i];
    __syncthreads();

    int w = tid >> 5, lane = tid & 31;
    int b = b0 + w;

    // first-zero prefix length via ballot over 32-chunks
    int n = HLEN;
    #pragma unroll
    for (int c = 0; c < (HLEN + 31) / 32; c++) {
        int idx = c * 32 + lane;
        int v = (idx < HLEN) ? ids[w][idx] : 1;
        unsigned m = __ballot_sync(0xffffffffu, v == 0);
        if (m) { n = c * 32 + __ffs(m) - 1; break; }
    }

    int ne = (b < g_first_inactive) ? n : 0;
    float inv_cnt = 1.0f / (float)(ne > 0 ? ne : 1);

    int half = lane >> 4;           // 0 = item half, 1 = cate half
    int q    = lane & 15;           // float4 index within the 64-dim half
    const float4* iW4 = (const float4*)iW;
    const float4* cW4 = (const float4*)cW;

    float4 acc = make_float4(0.f, 0.f, 0.f, 0.f);
    #pragma unroll 8
    for (int l = 0; l < ne; l++) {
        int id  = ids[w][l];
        int rid = half ? __ldg(&cate_list[id]) : id;
        const float4* tab = half ? cW4 : iW4;
        float4 v = __ldg(&tab[rid * 16 + q]);
        acc.x += v.x; acc.y += v.y; acc.z += v.z; acc.w += v.w;
    }
    float4 p = make_float4(acc.x * inv_cnt, acc.y * inv_cnt,
                           acc.z * inv_cnt, acc.w * inv_cnt);

    // user + item embeddings
    float4 uv = __ldg(&((const float4*)uW)[user[b] * 32 + lane]);
    int iid  = item[b];
    int rid2 = half ? __ldg(&cate_list[iid]) : iid;
    const float4* tab2 = half ? cW4 : iW4;
    float4 itv = __ldg(&tab2[rid2 * 16 + q]);

    // write tf32-split x
    uint2* xr = &g_xa[b * XD];
    store_split4(xr + lane * 4,       uv);
    store_split4(xr + 128 + lane * 4, itv);
    store_split4(xr + 256 + lane * 4, p);

    float4* sxr = (float4*)sx[w];
    sxr[lane]      = uv;
    sxr[32 + lane] = itv;
    sxr[64 + lane] = p;
    __syncthreads();

    // per-CTA reduce over 8 rows, then RED.ADD to global BN accumulators
    for (int f = tid; f < XD; f += 256) {
        float s1 = 0.f, s2 = 0.f;
        #pragma unroll
        for (int r = 0; r < RPB; r++) {
            float v = sx[r][f];
            s1 += v; s2 += v * v;
        }
        atomicAdd(&g_sum[f], s1);
        atomicAdd(&g_sumsq[f], s2);
    }
}

// compute BN scale/shift and self-reset accumulators for the next replay
__global__ void finalize_kernel(const float* __restrict__ gamma,
                                const float* __restrict__ beta) {
    int f = threadIdx.x;
    const float invN = 1.f / (float)BATCH;
    float mean = g_sum[f] * invN;
    float var  = g_sumsq[f] * invN - mean * mean;
    float inv  = rsqrtf(var + BN_EPS);
    float sc   = gamma[f] * inv;
    g_scale[f] = sc;
    g_shift[f] = beta[f] - mean * sc;
    g_sum[f]   = 0.f;
    g_sumsq[f] = 0.f;
    if (f == 0) g_first_inactive = BATCH;
}

// g_w1[n,k] = split(scale[k]*W1[n,k]) (0 for n>=200);
// g_c[n] = sum_k shift[k]*W1[n,k] + b1[n]
__global__ void convertw_kernel(const float* __restrict__ W1,
                                const float* __restrict__ b1) {
    __shared__ float red[12];
    int n = blockIdx.x;         // 0..255
    int k = threadIdx.x;        // 0..383
    float w = (n < H1) ? W1[n * XD + k] : 0.f;
    g_w1[n * XD + k] = tf32_split(w * g_scale[k]);
    float part = w * g_shift[k];
    #pragma unroll
    for (int off = 16; off; off >>= 1)
        part += __shfl_down_sync(0xffffffffu, part, off);
    if ((k & 31) == 0) red[k >> 5] = part;
    __syncthreads();
    if (k == 0) {
        float s = 0.f;
        #pragma unroll
        for (int i = 0; i < 12; i++) s += red[i];
        g_c[n] = s + ((n < H1) ? b1[n] : 0.f);
    }
}

// y1 = prelu(x @ (s∘W1)^T + c) via tf32 mma, hi/lo compensated (3 products).
// Operands preconverted — pure load->mma loop. M=4096 N=256 K=384.
// CTA: BM=64 BN=64 BK=16, 8 warps (4m x 2n), warp tile 16x32, 2-stage smem.
// grid (64, 4) = 256 CTAs -> ~2 CTAs/SM.
__global__ void __launch_bounds__(256, 2)
gemm1_kernel(const float* __restrict__ a1p) {
    __shared__ uint2 As[2][16][69];   // [k][m]
    __shared__ uint2 Bs[2][16][69];   // [k][n]

    int m0 = blockIdx.x * 64;
    int n0 = blockIdx.y * 64;
    int tid = threadIdx.x;
    int lane = tid & 31, wid = tid >> 5;
    int g = lane >> 2, tig = lane & 3;
    int wm = wid & 3;    // 4 m-warps: 16 rows each
    int wn = wid >> 2;   // 2 n-warps: 32 cols each

    // loaders: row lm 0..63, k-quad kq
    int lm = tid >> 2;
    int kq = (tid & 3) * 4;
    const uint2* gA = g_xa + (m0 + lm) * XD;
    const uint2* gB = g_w1 + (n0 + lm) * XD;

    float4 acc[4];
    #pragma unroll
    for (int nt = 0; nt < 4; nt++) acc[nt] = make_float4(0.f, 0.f, 0.f, 0.f);

    // prologue: k-tile 0
    uint4 ra0 = *(const uint4*)&gA[kq];
    uint4 ra1 = *(const uint4*)&gA[kq + 2];
    uint4 rb0 = *(const uint4*)&gB[kq];
    uint4 rb1 = *(const uint4*)&gB[kq + 2];
    As[0][kq + 0][lm] = make_uint2(ra0.x, ra0.y);
    As[0][kq + 1][lm] = make_uint2(ra0.z, ra0.w);
    As[0][kq + 2][lm] = make_uint2(ra1.x, ra1.y);
    As[0][kq + 3][lm] = make_uint2(ra1.z, ra1.w);
    Bs[0][kq + 0][lm] = make_uint2(rb0.x, rb0.y);
    Bs[0][kq + 1][lm] = make_uint2(rb0.z, rb0.w);
    Bs[0][kq + 2][lm] = make_uint2(rb1.x, rb1.y);
    Bs[0][kq + 3][lm] = make_uint2(rb1.z, rb1.w);
    __syncthreads();

    #pragma unroll 1
    for (int it = 0; it < 24; it++) {
        int cur = it & 1;
        uint4 na0, na1, nb0, nb1;
        if (it < 23) {
            int kt = (it + 1) * 16;
            na0 = *(const uint4*)&gA[kt + kq];
            na1 = *(const uint4*)&gA[kt + kq + 2];
            nb0 = *(const uint4*)&gB[kt + kq];
            nb1 = *(const uint4*)&gB[kt + kq + 2];
        }

        #pragma unroll
        for (int ks = 0; ks < 2; ks++) {
            int kb = ks * 8;
            uint2 a0 = As[cur][kb + tig][wm * 16 + g];
            uint2 a1 = As[cur][kb + tig][wm * 16 + g + 8];
            uint2 a2 = As[cur][kb + tig + 4][wm * 16 + g];
            uint2 a3 = As[cur][kb + tig + 4][wm * 16 + g + 8];
            #pragma unroll
            for (int nt = 0; nt < 4; nt++) {
                uint2 b0 = Bs[cur][kb + tig][wn * 32 + nt * 8 + g];
                uint2 b1 = Bs[cur][kb + tig + 4][wn * 32 + nt * 8 + g];
                mma_tf32(acc[nt], a0.x, a1.x, a2.x, a3.x, b0.x, b1.x);
                mma_tf32(acc[nt], a0.x, a1.x, a2.x, a3.x, b0.y, b1.y);
                mma_tf32(acc[nt], a0.y, a1.y, a2.y, a3.y, b0.x, b1.x);
            }
        }

        if (it < 23) {
            int nxt = cur ^ 1;
            As[nxt][kq + 0][lm] = make_uint2(na0.x, na0.y);
            As[nxt][kq + 1][lm] = make_uint2(na0.z, na0.w);
            As[nxt][kq + 2][lm] = make_uint2(na1.x, na1.y);
            As[nxt][kq + 3][lm] = make_uint2(na1.z, na1.w);
            Bs[nxt][kq + 0][lm] = make_uint2(nb0.x, nb0.y);
            Bs[nxt][kq + 1][lm] = make_uint2(nb0.z, nb0.w);
            Bs[nxt][kq + 2][lm] = make_uint2(nb1.x, nb1.y);
            Bs[nxt][kq + 3][lm] = make_uint2(nb1.z, nb1.w);
        }
        __syncthreads();
    }

    // epilogue: + g_c (bias folded), prelu, write y1
    float alpha = __ldg(a1p);
    int row = m0 + wm * 16 + g;
    #pragma unroll
    for (int nt = 0; nt < 4; nt++) {
        int col = n0 + wn * 32 + nt * 8 + tig * 2;
        if (col < H1) {
            float c0 = g_c[col], c1 = g_c[col + 1];
            float v0 = acc[nt].x + c0;
            float v1 = acc[nt].y + c1;
            float v2 = acc[nt].z + c0;
            float v3 = acc[nt].w + c1;
            v0 = (v0 >= 0.f) ? v0 : alpha * v0;
            v1 = (v1 >= 0.f) ? v1 : alpha * v1;
            v2 = (v2 >= 0.f) ? v2 : alpha * v2;
            v3 = (v3 >= 0.f) ? v3 : alpha * v3;
            *(float2*)&g_y1[row * H1 + col]       = make_float2(v0, v1);
            *(float2*)&g_y1[(row + 8) * H1 + col] = make_float2(v2, v3);
        }
    }
}

// y2 = prelu(y1 @ W2^T + b2); logits = y2 @ W3^T + b3; softmax — fused.
// M=4096 N=80 K=200; BM=64 BN=80 BK=8, 256 threads, 4x5, double-buffered.
__global__ void gemm2_out_kernel(const float* __restrict__ W2,
                                 const float* __restrict__ b2,
                                 const float* __restrict__ a2p,
                                 const float* __restrict__ W3,
                                 const float* __restrict__ b3,
                                 float* __restrict__ out) {
    __shared__ float As[2][8][68];
    __shared__ float Bs[2][8][84];
    __shared__ float sy[64][81];
    __shared__ float sw3[2 * H2];

    int m0 = blockIdx.x * 64;
    int tid = threadIdx.x;
    int tx = tid & 15, ty = tid >> 4;     // tx -> n (5 each), ty -> m (4 each)
    int lk2 = (tid & 3) * 2, lm = tid >> 2;       // A loader: float2 along k
    int bn = tid >> 1, bq = (tid & 1) * 4;        // B loader: threads<160 load float4

    if (tid < 2 * H2) sw3[tid] = W3[tid];

    float acc[4][5];
    #pragma unroll
    for (int i = 0; i < 4; i++)
        #pragma unroll
        for (int j = 0; j < 5; j++) acc[i][j] = 0.f;

    // prologue
    float2 pa = *(const float2*)&g_y1[(m0 + lm) * H1 + lk2];
    float4 pb = (tid < 160) ? *(const float4*)&W2[bn * H1 + bq]
                            : make_float4(0.f, 0.f, 0.f, 0.f);
    As[0][lk2 + 0][lm] = pa.x;
    As[0][lk2 + 1][lm] = pa.y;
    if (tid < 160) {
        Bs[0][bq + 0][bn] = pb.x; Bs[0][bq + 1][bn] = pb.y;
        Bs[0][bq + 2][bn] = pb.z; Bs[0][bq + 3][bn] = pb.w;
    }
    __syncthreads();

    #pragma unroll 1
    for (int it = 0; it < 25; it++) {
        int cur = it & 1;
        float2 na; float4 nb;
        int k0n = (it + 1) * 8;
        if (it < 24) {
            na = *(const float2*)&g_y1[(m0 + lm) * H1 + k0n + lk2];
            if (tid < 160) nb = *(const float4*)&W2[bn * H1 + k0n + bq];
        }
        #pragma unroll
        for (int kk = 0; kk < 8; kk++) {
            float4 ta = *(const float4*)&As[cur][kk][ty * 4];
            float a[4] = {ta.x, ta.y, ta.z, ta.w};
            float bb[5];
            #pragma unroll
            for (int j = 0; j < 5; j++) bb[j] = Bs[cur][kk][tx * 5 + j];
            #pragma unroll
            for (int i = 0; i < 4; i++)
                #pragma unroll
                for (int j = 0; j < 5; j++) acc[i][j] += a[i] * bb[j];
        }
        if (it < 24) {
            int nxt = cur ^ 1;
            As[nxt][lk2 + 0][lm] = na.x;
            As[nxt][lk2 + 1][lm] = na.y;
            if (tid < 160) {
                Bs[nxt][bq + 0][bn] = nb.x; Bs[nxt][bq + 1][bn] = nb.y;
                Bs[nxt][bq + 2][bn] = nb.z; Bs[nxt][bq + 3][bn] = nb.w;
            }
        }
        __syncthreads();
    }

    float alpha = a2p[0];
    #pragma unroll
    for (int i = 0; i < 4; i++)
        #pragma unroll
        for (int j = 0; j < 5; j++) {
            float v = acc[i][j] + b2[tx * 5 + j];
            v = (v >= 0.f) ? v : alpha * v;
            sy[ty * 4 + i][tx * 5 + j] = v;
        }
    __syncthreads();

    // logits + softmax: 4 threads per row, 20 dims each, shuffle-combine
    int row = tid >> 2, part = tid & 3;
    float s0 = 0.f, s1 = 0.f;
    int kbase = part * 20;
    #pragma unroll
    for (int k = 0; k < 20; k++) {
        float v = sy[row][kbase + k];
        s0 += v * sw3[kbase + k];
        s1 += v * sw3[H2 + kbase + k];
    }
    s0 += __shfl_down_sync(0xffffffffu, s0, 2, 4);
    s0 += __shfl_down_sync(0xffffffffu, s0, 1, 4);
    s1 += __shfl_down_sync(0xffffffffu, s1, 2, 4);
    s1 += __shfl_down_sync(0xffffffffu, s1, 1, 4);
    if (part == 0) {
        float l0 = s0 + b3[0], l1 = s1 + b3[1];
        float m = fmaxf(l0, l1);
        float e0 = expf(l0 - m), e1 = expf(l1 - m);
        float inv = 1.f / (e0 + e1);
        out[(m0 + row) * 2 + 0] = e0 * inv;
        out[(m0 + row) * 2 + 1] = e1 * inv;
    }
}

// ---------------- launch ----------------
extern "C" void kernel_launch(void* const* d_in, const int* in_sizes, int n_in,
                              void* d_out, int out_size) {
    const int*   user      = (const int*)d_in[0];
    const int*   item      = (const int*)d_in[1];
    const int*   history   = (const int*)d_in[2];
    // d_in[3] = length (unused; semantics derived from history zeros)
    const int*   cate_list = (const int*)d_in[4];
    const float* uW        = (const float*)d_in[5];
    const float* iW        = (const float*)d_in[6];
    const float* cW        = (const float*)d_in[7];
    const float* gamma     = (const float*)d_in[8];
    const float* beta      = (const float*)d_in[9];
    const float* W1        = (const float*)d_in[10];
    const float* b1        = (const float*)d_in[11];
    const float* a1        = (const float*)d_in[12];
    const float* W2        = (const float*)d_in[13];
    const float* b2        = (const float*)d_in[14];
    const float* a2        = (const float*)d_in[15];
    const float* W3        = (const float*)d_in[16];
    const float* b3        = (const float*)d_in[17];
    float* out = (float*)d_out;

    scan_kernel<<<16, 256>>>(history);
    embed_kernel<<<BATCH / RPB, 256>>>(user, item, history, cate_list, uW, iW, cW);
    finalize_kernel<<<1, 384>>>(gamma, beta);
    convertw_kernel<<<N1P, 384>>>(W1, b1);
    dim3 g1(BATCH / 64, 4);
    gemm1_kernel<<<g1, 256>>>(a1);
    gemm2_out_kernel<<<BATCH / 64, 256>>>(W2, b2, a2, W3, b3, out);
}

// round 10
// speedup vs baseline: 1.0624x; 1.0624x over previous
#include <cuda_runtime.h>
#include <math.h>
#include <stdint.h>

#define BATCH 4096
#define HLEN  200
#define XD    384
#define H1    200
#define N1P   256     // W1 rows padded
#define H2    80
#define BN_EPS 1e-5f
#define RPB   8       // rows per embed CTA

// ---------------- device scratch (static allocation only) ----------------
__device__ __align__(16) uint2 g_xa[BATCH * XD];   // tf32 (hi,lo) of raw x, [b][k]
__device__ __align__(16) uint2 g_w1[N1P * XD];     // tf32 (hi,lo) of scale∘W1, [n][k], zero-padded
__device__ float g_c[N1P];                         // sum_k shift[k]*W1[n,k] + b1[n]
__device__ float g_y1[BATCH * H1];
__device__ float g_sum[XD];                        // zeroed; gemm2 block0 resets after use
__device__ float g_sumsq[XD];
__device__ int   g_first_inactive = BATCH;         // gemm2 block0 resets after use

// ---------------- helpers ----------------
__device__ __forceinline__ uint32_t f2tf32(float f) {
    uint32_t r;
    asm("cvt.rna.tf32.f32 %0, %1;" : "=r"(r) : "f"(f));
    return r;
}
__device__ __forceinline__ uint2 tf32_split(float f) {
    uint32_t hi = f2tf32(f);
    float lo = f - __uint_as_float(hi);
    return make_uint2(hi, f2tf32(lo));
}
__device__ __forceinline__ void store_split4(uint2* dst, float4 v) {
    uint2 s0 = tf32_split(v.x), s1 = tf32_split(v.y);
    uint2 s2 = tf32_split(v.z), s3 = tf32_split(v.w);
    *(uint4*)(dst)     = make_uint4(s0.x, s0.y, s1.x, s1.y);
    *(uint4*)(dst + 2) = make_uint4(s2.x, s2.y, s3.x, s3.y);
}
__device__ __forceinline__ void mma_tf32(float4& d,
                                         uint32_t a0, uint32_t a1,
                                         uint32_t a2, uint32_t a3,
                                         uint32_t b0, uint32_t b1) {
    asm volatile(
        "mma.sync.aligned.m16n8k8.row.col.f32.tf32.tf32.f32 "
        "{%0,%1,%2,%3}, {%4,%5,%6,%7}, {%8,%9}, {%0,%1,%2,%3};"
        : "+f"(d.x), "+f"(d.y), "+f"(d.z), "+f"(d.w)
        : "r"(a0), "r"(a1), "r"(a2), "r"(a3), "r"(b0), "r"(b1));
}
__device__ __forceinline__ void cp16(uint32_t smem_dst, const void* gsrc) {
    asm volatile("cp.async.cg.shared.global [%0], [%1], 16;"
                 :: "r"(smem_dst), "l"(gsrc));
}
__device__ __forceinline__ void cp_commit() {
    asm volatile("cp.async.commit_group;" ::: "memory");
}
__device__ __forceinline__ void cp_wait0() {
    asm volatile("cp.async.wait_group 0;" ::: "memory");
}

// ---------------- kernels ----------------

// outer-break semantics: first row b with history[b,0]==0 deactivates rows >= b
__global__ void scan_kernel(const int* __restrict__ history) {
    int b = blockIdx.x * blockDim.x + threadIdx.x;
    if (b < BATCH && history[b * HLEN] == 0) atomicMin(&g_first_inactive, b);
}

// warp-per-row embedding gather + pool; writes tf32-split x; fused BN sums.
__global__ void embed_kernel(const int* __restrict__ user,
                             const int* __restrict__ item,
                             const int* __restrict__ history,
                             const int* __restrict__ cate_list,
                             const float* __restrict__ uW,   // [100000,128]
                             const float* __restrict__ iW,   // [100000,64]
                             const float* __restrict__ cW) { // [1000,64]
    __shared__ int   ids[RPB][HLEN];
    __shared__ float sx[RPB][XD];     // per-row x values for BN reduction

    int b0  = blockIdx.x * RPB;
    int tid = threadIdx.x;

    for (int i = tid; i < RPB * HLEN; i += 256)
        ids[i / HLEN][i % HLEN] = history[b0 * HLEN + i];
    __syncthreads();

    int w = tid >> 5, lane = tid & 31;
    int b = b0 + w;

    // first-zero prefix length via ballot over 32-chunks
    int n = HLEN;
    #pragma unroll
    for (int c = 0; c < (HLEN + 31) / 32; c++) {
        int idx = c * 32 + lane;
        int v = (idx < HLEN) ? ids[w][idx] : 1;
        unsigned m = __ballot_sync(0xffffffffu, v == 0);
        if (m) { n = c * 32 + __ffs(m) - 1; break; }
    }

    int ne = (b < g_first_inactive) ? n : 0;
    float inv_cnt = 1.0f / (float)(ne > 0 ? ne : 1);

    int half = lane >> 4;           // 0 = item half, 1 = cate half
    int q    = lane & 15;           // float4 index within the 64-dim half
    const float4* iW4 = (const float4*)iW;
    const float4* cW4 = (const float4*)cW;

    float4 acc = make_float4(0.f, 0.f, 0.f, 0.f);
    #pragma unroll 8
    for (int l = 0; l < ne; l++) {
        int id  = ids[w][l];
        int rid = half ? __ldg(&cate_list[id]) : id;
        const float4* tab = half ? cW4 : iW4;
        float4 v = __ldg(&tab[rid * 16 + q]);
        acc.x += v.x; acc.y += v.y; acc.z += v.z; acc.w += v.w;
    }
    float4 p = make_float4(acc.x * inv_cnt, acc.y * inv_cnt,
                           acc.z * inv_cnt, acc.w * inv_cnt);

    // user + item embeddings
    float4 uv = __ldg(&((const float4*)uW)[user[b] * 32 + lane]);
    int iid  = item[b];
    int rid2 = half ? __ldg(&cate_list[iid]) : iid;
    const float4* tab2 = half ? cW4 : iW4;
    float4 itv = __ldg(&tab2[rid2 * 16 + q]);

    // write tf32-split x
    uint2* xr = &g_xa[b * XD];
    store_split4(xr + lane * 4,       uv);
    store_split4(xr + 128 + lane * 4, itv);
    store_split4(xr + 256 + lane * 4, p);

    float4* sxr = (float4*)sx[w];
    sxr[lane]      = uv;
    sxr[32 + lane] = itv;
    sxr[64 + lane] = p;
    __syncthreads();

    // per-CTA reduce over 8 rows, then RED.ADD to global BN accumulators
    for (int f = tid; f < XD; f += 256) {
        float s1 = 0.f, s2 = 0.f;
        #pragma unroll
        for (int r = 0; r < RPB; r++) {
            float v = sx[r][f];
            s1 += v; s2 += v * v;
        }
        atomicAdd(&g_sum[f], s1);
        atomicAdd(&g_sumsq[f], s2);
    }
}

// Self-contained BN fold + weight convert:
//   scale[k] = gamma[k]*rsqrt(var[k]+eps); shift[k] = beta[k]-mean[k]*scale[k]
//   g_w1[n,k] = split(scale[k]*W1[n,k]) (0 for n>=200)
//   g_c[n] = sum_k shift[k]*W1[n,k] + b1[n]
// grid 256 (one n per block), 96 threads x float4.
__global__ void convertw_kernel(const float* __restrict__ W1,
                                const float* __restrict__ b1,
                                const float* __restrict__ gamma,
                                const float* __restrict__ beta) {
    __shared__ float red[3];
    int n = blockIdx.x;
    int t = threadIdx.x;         // 0..95
    int k = t * 4;
    const float invN = 1.f / (float)BATCH;

    float4 s4 = *(const float4*)&g_sum[k];
    float4 q4 = *(const float4*)&g_sumsq[k];
    float4 gm = __ldg((const float4*)&gamma[k]);
    float4 bt = __ldg((const float4*)&beta[k]);
    float4 w4 = (n < H1) ? __ldg((const float4*)&W1[n * XD + k])
                         : make_float4(0.f, 0.f, 0.f, 0.f);

    float sv[4] = {s4.x, s4.y, s4.z, s4.w};
    float qv[4] = {q4.x, q4.y, q4.z, q4.w};
    float gv[4] = {gm.x, gm.y, gm.z, gm.w};
    float bv[4] = {bt.x, bt.y, bt.z, bt.w};
    float wv[4] = {w4.x, w4.y, w4.z, w4.w};

    uint2 o[4];
    float part = 0.f;
    #pragma unroll
    for (int j = 0; j < 4; j++) {
        float mean = sv[j] * invN;
        float var  = qv[j] * invN - mean * mean;
        float inv  = rsqrtf(var + BN_EPS);
        float sc   = gv[j] * inv;
        float sf   = bv[j] - mean * sc;
        o[j] = tf32_split(wv[j] * sc);
        part += wv[j] * sf;
    }
    uint2* dst = &g_w1[n * XD + k];
    *(uint4*)(dst)     = make_uint4(o[0].x, o[0].y, o[1].x, o[1].y);
    *(uint4*)(dst + 2) = make_uint4(o[2].x, o[2].y, o[3].x, o[3].y);

    #pragma unroll
    for (int off = 16; off; off >>= 1)
        part += __shfl_down_sync(0xffffffffu, part, off);
    if ((t & 31) == 0) red[t >> 5] = part;
    __syncthreads();
    if (t == 0)
        g_c[n] = red[0] + red[1] + red[2] + ((n < H1) ? __ldg(&b1[n]) : 0.f);
}

// y1 = prelu(x @ (s∘W1)^T + c) via tf32 mma, hi/lo compensated (3 products).
// cp.async 2-stage pipeline; smem [m][k] pitch 20 (conflict-free fragments).
// M=4096 N=256 K=384. CTA: BM=64 BN=64 BK=16, 8 warps (4m x 2n), warp 16x32.
// Dead column tiles (>=200) skip mma + B-fragment loads.
__global__ void __launch_bounds__(256, 2)
gemm1_kernel(const float* __restrict__ a1p) {
    __shared__ uint2 As[2][64][20];   // [stage][m][k]
    __shared__ uint2 Bs[2][64][20];   // [stage][n][k]

    int m0 = blockIdx.x * 64;
    int n0 = blockIdx.y * 64;
    int tid = threadIdx.x;
    int lane = tid & 31, wid = tid >> 5;
    int g = lane >> 2, tig = lane & 3;
    int wm = wid & 3;    // 4 m-warps: 16 rows each
    int wn = wid >> 2;   // 2 n-warps: 32 cols each

    // loader: row lm 0..63, k-quad kq (2 x 16B per tile per matrix)
    int lm = tid >> 2;
    int kq = (tid & 3) * 4;
    const uint2* gA = g_xa + (m0 + lm) * XD + kq;
    const uint2* gB = g_w1 + (n0 + lm) * XD + kq;
    uint32_t sA = (uint32_t)__cvta_generic_to_shared(&As[0][lm][kq]);
    uint32_t sB = (uint32_t)__cvta_generic_to_shared(&Bs[0][lm][kq]);
    const uint32_t STAGE = 64 * 20 * 8;   // 10240 B

    bool ntv[4];
    #pragma unroll
    for (int nt = 0; nt < 4; nt++) ntv[nt] = (n0 + wn * 32 + nt * 8) < H1;

    float4 acc[4];
    #pragma unroll
    for (int nt = 0; nt < 4; nt++) acc[nt] = make_float4(0.f, 0.f, 0.f, 0.f);

    // prologue: tile 0 -> stage 0
    cp16(sA,      gA);     cp16(sA + 16, gA + 2);
    cp16(sB,      gB);     cp16(sB + 16, gB + 2);
    cp_commit();

    #pragma unroll 1
    for (int it = 0; it < 24; it++) {
        cp_wait0();
        __syncthreads();
        if (it < 23) {
            uint32_t off = ((it + 1) & 1) * STAGE;
            const uint2* pa = gA + (it + 1) * 16;
            const uint2* pb = gB + (it + 1) * 16;
            cp16(sA + off,      pa);     cp16(sA + off + 16, pa + 2);
            cp16(sB + off,      pb);     cp16(sB + off + 16, pb + 2);
        }
        cp_commit();

        int cur = it & 1;
        #pragma unroll
        for (int ks = 0; ks < 2; ks++) {
            int kb = ks * 8;
            uint2 a0 = As[cur][wm * 16 + g][kb + tig];
            uint2 a1 = As[cur][wm * 16 + g + 8][kb + tig];
            uint2 a2 = As[cur][wm * 16 + g][kb + tig + 4];
            uint2 a3 = As[cur][wm * 16 + g + 8][kb + tig + 4];
            #pragma unroll
            for (int nt = 0; nt < 4; nt++) {
                if (ntv[nt]) {
                    uint2 b0 = Bs[cur][wn * 32 + nt * 8 + g][kb + tig];
                    uint2 b1 = Bs[cur][wn * 32 + nt * 8 + g][kb + tig + 4];
                    mma_tf32(acc[nt], a0.x, a1.x, a2.x, a3.x, b0.x, b1.x);
                    mma_tf32(acc[nt], a0.x, a1.x, a2.x, a3.x, b0.y, b1.y);
                    mma_tf32(acc[nt], a0.y, a1.y, a2.y, a3.y, b0.x, b1.x);
                }
            }
        }
    }

    // epilogue: + g_c (bias + BN shift folded), prelu, write y1
    float alpha = __ldg(a1p);
    int row = m0 + wm * 16 + g;
    #pragma unroll
    for (int nt = 0; nt < 4; nt++) {
        int col = n0 + wn * 32 + nt * 8 + tig * 2;
        if (col < H1) {
            float c0 = g_c[col], c1 = g_c[col + 1];
            float v0 = acc[nt].x + c0;
            float v1 = acc[nt].y + c1;
            float v2 = acc[nt].z + c0;
            float v3 = acc[nt].w + c1;
            v0 = (v0 >= 0.f) ? v0 : alpha * v0;
            v1 = (v1 >= 0.f) ? v1 : alpha * v1;
            v2 = (v2 >= 0.f) ? v2 : alpha * v2;
            v3 = (v3 >= 0.f) ? v3 : alpha * v3;
            *(float2*)&g_y1[row * H1 + col]       = make_float2(v0, v1);
            *(float2*)&g_y1[(row + 8) * H1 + col] = make_float2(v2, v3);
        }
    }
}

// y2 = prelu(y1 @ W2^T + b2); logits = y2 @ W3^T + b3; softmax — fused.
// Block 0 also resets BN accumulators for the next graph replay.
// M=4096 N=80 K=200; BM=64 BN=80 BK=8, 256 threads, 4x5, double-buffered.
__global__ void gemm2_out_kernel(const float* __restrict__ W2,
                                 const float* __restrict__ b2,
                                 const float* __restrict__ a2p,
                                 const float* __restrict__ W3,
                                 const float* __restrict__ b3,
                                 float* __restrict__ out) {
    __shared__ float As[2][8][68];
    __shared__ float Bs[2][8][84];
    __shared__ float sy[64][81];
    __shared__ float sw3[2 * H2];

    int m0 = blockIdx.x * 64;
    int tid = threadIdx.x;

    // next-replay resets (safe: convertw consumed these before gemm1/gemm2 run)
    if (blockIdx.x == 0) {
        if (tid < 256) { g_sum[tid] = 0.f; g_sumsq[tid] = 0.f; }
        if (tid < XD - 256) { g_sum[256 + tid] = 0.f; g_sumsq[256 + tid] = 0.f; }
        if (tid == 0) g_first_inactive = BATCH;
    }

    int tx = tid & 15, ty = tid >> 4;     // tx -> n (5 each), ty -> m (4 each)
    int lk2 = (tid & 3) * 2, lm = tid >> 2;       // A loader: float2 along k
    int bn = tid >> 1, bq = (tid & 1) * 4;        // B loader: threads<160 load float4

    if (tid < 2 * H2) sw3[tid] = W3[tid];

    float acc[4][5];
    #pragma unroll
    for (int i = 0; i < 4; i++)
        #pragma unroll
        for (int j = 0; j < 5; j++) acc[i][j] = 0.f;

    // prologue
    float2 pa = *(const float2*)&g_y1[(m0 + lm) * H1 + lk2];
    float4 pb = (tid < 160) ? *(const float4*)&W2[bn * H1 + bq]
                            : make_float4(0.f, 0.f, 0.f, 0.f);
    As[0][lk2 + 0][lm] = pa.x;
    As[0][lk2 + 1][lm] = pa.y;
    if (tid < 160) {
        Bs[0][bq + 0][bn] = pb.x; Bs[0][bq + 1][bn] = pb.y;
        Bs[0][bq + 2][bn] = pb.z; Bs[0][bq + 3][bn] = pb.w;
    }
    __syncthreads();

    #pragma unroll 1
    for (int it = 0; it < 25; it++) {
        int cur = it & 1;
        float2 na; float4 nb;
        int k0n = (it + 1) * 8;
        if (it < 24) {
            na = *(const float2*)&g_y1[(m0 + lm) * H1 + k0n + lk2];
            if (tid < 160) nb = *(const float4*)&W2[bn * H1 + k0n + bq];
        }
        #pragma unroll
        for (int kk = 0; kk < 8; kk++) {
            float4 ta = *(const float4*)&As[cur][kk][ty * 4];
            float a[4] = {ta.x, ta.y, ta.z, ta.w};
            float bb[5];
            #pragma unroll
            for (int j = 0; j < 5; j++) bb[j] = Bs[cur][kk][tx * 5 + j];
            #pragma unroll
            for (int i = 0; i < 4; i++)
                #pragma unroll
                for (int j = 0; j < 5; j++) acc[i][j] += a[i] * bb[j];
        }
        if (it < 24) {
            int nxt = cur ^ 1;
            As[nxt][lk2 + 0][lm] = na.x;
            As[nxt][lk2 + 1][lm] = na.y;
            if (tid < 160) {
                Bs[nxt][bq + 0][bn] = nb.x; Bs[nxt][bq + 1][bn] = nb.y;
                Bs[nxt][bq + 2][bn] = nb.z; Bs[nxt][bq + 3][bn] = nb.w;
            }
        }
        __syncthreads();
    }

    float alpha = a2p[0];
    #pragma unroll
    for (int i = 0; i < 4; i++)
        #pragma unroll
        for (int j = 0; j < 5; j++) {
            float v = acc[i][j] + b2[tx * 5 + j];
            v = (v >= 0.f) ? v : alpha * v;
            sy[ty * 4 + i][tx * 5 + j] = v;
        }
    __syncthreads();

    // logits + softmax: 4 threads per row, 20 dims each, shuffle-combine
    int row = tid >> 2, part = tid & 3;
    float s0 = 0.f, s1 = 0.f;
    int kbase = part * 20;
    #pragma unroll
    for (int k = 0; k < 20; k++) {
        float v = sy[row][kbase + k];
        s0 += v * sw3[kbase + k];
        s1 += v * sw3[H2 + kbase + k];
    }
    s0 += __shfl_down_sync(0xffffffffu, s0, 2, 4);
    s0 += __shfl_down_sync(0xffffffffu, s0, 1, 4);
    s1 += __shfl_down_sync(0xffffffffu, s1, 2, 4);
    s1 += __shfl_down_sync(0xffffffffu, s1, 1, 4);
    if (part == 0) {
        float l0 = s0 + b3[0], l1 = s1 + b3[1];
        float m = fmaxf(l0, l1);
        float e0 = expf(l0 - m), e1 = expf(l1 - m);
        float inv = 1.f / (e0 + e1);
        out[(m0 + row) * 2 + 0] = e0 * inv;
        out[(m0 + row) * 2 + 1] = e1 * inv;
    }
}

// ---------------- launch ----------------
extern "C" void kernel_launch(void* const* d_in, const int* in_sizes, int n_in,
                              void* d_out, int out_size) {
    const int*   user      = (const int*)d_in[0];
    const int*   item      = (const int*)d_in[1];
    const int*   history   = (const int*)d_in[2];
    // d_in[3] = length (unused; semantics derived from history zeros)
    const int*   cate_list = (const int*)d_in[4];
    const float* uW        = (const float*)d_in[5];
    const float* iW        = (const float*)d_in[6];
    const float* cW        = (const float*)d_in[7];
    const float* gamma     = (const float*)d_in[8];
    const float* beta      = (const float*)d_in[9];
    const float* W1        = (const float*)d_in[10];
    const float* b1        = (const float*)d_in[11];
    const float* a1        = (const float*)d_in[12];
    const float* W2        = (const float*)d_in[13];
    const float* b2        = (const float*)d_in[14];
    const float* a2        = (const float*)d_in[15];
    const float* W3        = (const float*)d_in[16];
    const float* b3        = (const float*)d_in[17];
    float* out = (float*)d_out;

    scan_kernel<<<16, 256>>>(history);
    embed_kernel<<<BATCH / RPB, 256>>>(user, item, history, cate_list, uW, iW, cW);
    convertw_kernel<<<N1P, 96>>>(W1, b1, gamma, beta);
    dim3 g1(BATCH / 64, 4);
    gemm1_kernel<<<g1, 256>>>(a1);
    gemm2_out_kernel<<<BATCH / 64, 256>>>(W2, b2, a2, W3, b3, out);
}

// round 11
// speedup vs baseline: 1.1580x; 1.0900x over previous
#include <cuda_runtime.h>
#include <math.h>
#include <stdint.h>

#define BATCH 4096
#define HLEN  200
#define XD    384
#define H1    200
#define N1P   256     // W1 rows padded
#define H2    80
#define BN_EPS 1e-5f
#define RPB   8       // rows per embed CTA

// ---------------- device scratch (static allocation only) ----------------
__device__ __align__(16) uint2 g_xa[BATCH * XD];   // tf32 (hi,lo) of raw x, [b][k]
__device__ __align__(16) uint2 g_w1[N1P * XD];     // tf32 (hi,lo) of scale∘W1, [n][k], zero-padded
__device__ float g_c[N1P];                         // sum_k shift[k]*W1[n,k] + b1[n]
__device__ float g_y1[BATCH * H1];
__device__ float g_sum[XD];                        // zeroed; gemm2 block0 resets after use
__device__ float g_sumsq[XD];
__device__ int   g_first_inactive = BATCH;         // gemm2 block0 resets after use

// ---------------- helpers ----------------
__device__ __forceinline__ uint32_t f2tf32(float f) {
    uint32_t r;
    asm("cvt.rna.tf32.f32 %0, %1;" : "=r"(r) : "f"(f));
    return r;
}
__device__ __forceinline__ uint2 tf32_split(float f) {
    uint32_t hi = f2tf32(f);
    float lo = f - __uint_as_float(hi);
    return make_uint2(hi, f2tf32(lo));
}
__device__ __forceinline__ void store_split4(uint2* dst, float4 v) {
    uint2 s0 = tf32_split(v.x), s1 = tf32_split(v.y);
    uint2 s2 = tf32_split(v.z), s3 = tf32_split(v.w);
    *(uint4*)(dst)     = make_uint4(s0.x, s0.y, s1.x, s1.y);
    *(uint4*)(dst + 2) = make_uint4(s2.x, s2.y, s3.x, s3.y);
}
__device__ __forceinline__ void mma_tf32(float4& d,
                                         uint32_t a0, uint32_t a1,
                                         uint32_t a2, uint32_t a3,
                                         uint32_t b0, uint32_t b1) {
    asm volatile(
        "mma.sync.aligned.m16n8k8.row.col.f32.tf32.tf32.f32 "
        "{%0,%1,%2,%3}, {%4,%5,%6,%7}, {%8,%9}, {%0,%1,%2,%3};"
        : "+f"(d.x), "+f"(d.y), "+f"(d.z), "+f"(d.w)
        : "r"(a0), "r"(a1), "r"(a2), "r"(a3), "r"(b0), "r"(b1));
}
__device__ __forceinline__ void cp16(uint32_t smem_dst, const void* gsrc) {
    asm volatile("cp.async.cg.shared.global [%0], [%1], 16;"
                 :: "r"(smem_dst), "l"(gsrc));
}
__device__ __forceinline__ void cp_commit() {
    asm volatile("cp.async.commit_group;" ::: "memory");
}
__device__ __forceinline__ void cp_wait0() {
    asm volatile("cp.async.wait_group 0;" ::: "memory");
}
__device__ __forceinline__ void cp_wait1() {
    asm volatile("cp.async.wait_group 1;" ::: "memory");
}

// ---------------- kernels ----------------

// outer-break semantics: first row b with history[b,0]==0 deactivates rows >= b
__global__ void scan_kernel(const int* __restrict__ history) {
    int b = blockIdx.x * blockDim.x + threadIdx.x;
    if (b < BATCH && history[b * HLEN] == 0) atomicMin(&g_first_inactive, b);
}

// warp-per-row embedding gather + pool; writes tf32-split x; fused BN sums.
// cate ids pre-gathered into smem pairs -> gather loop is 1 LDS + 1 LDG per l.
__global__ void embed_kernel(const int* __restrict__ user,
                             const int* __restrict__ item,
                             const int* __restrict__ history,
                             const int* __restrict__ cate_list,
                             const float* __restrict__ uW,   // [100000,128]
                             const float* __restrict__ iW,   // [100000,64]
                             const float* __restrict__ cW) { // [1000,64]
    __shared__ int   ids[RPB][HLEN];
    __shared__ int2  pairs[RPB][HLEN];   // (item_id, cate_id)
    __shared__ float sx[RPB][XD];        // per-row x values for BN reduction

    int b0  = blockIdx.x * RPB;
    int tid = threadIdx.x;

    for (int i = tid; i < RPB * HLEN; i += 256)
        ids[i / HLEN][i % HLEN] = history[b0 * HLEN + i];
    __syncthreads();

    int w = tid >> 5, lane = tid & 31;
    int b = b0 + w;

    // first-zero prefix length via ballot over 32-chunks
    int n = HLEN;
    #pragma unroll
    for (int c = 0; c < (HLEN + 31) / 32; c++) {
        int idx = c * 32 + lane;
        int v = (idx < HLEN) ? ids[w][idx] : 1;
        unsigned m = __ballot_sync(0xffffffffu, v == 0);
        if (m) { n = c * 32 + __ffs(m) - 1; break; }
    }

    // batched (id, cate_id) pair build — high-MLP parallel phase
    for (int i = tid; i < RPB * HLEN; i += 256) {
        int id = ids[i / HLEN][i % HLEN];
        pairs[i / HLEN][i % HLEN] = make_int2(id, __ldg(&cate_list[id]));
    }
    __syncthreads();

    int ne = (b < g_first_inactive) ? n : 0;
    float inv_cnt = 1.0f / (float)(ne > 0 ? ne : 1);

    int half = lane >> 4;           // 0 = item half, 1 = cate half
    int q    = lane & 15;           // float4 index within the 64-dim half
    const float4* tab = half ? (const float4*)cW : (const float4*)iW;

    float4 acc = make_float4(0.f, 0.f, 0.f, 0.f);
    #pragma unroll 4
    for (int l = 0; l < ne; l++) {
        int2 p = pairs[w][l];              // LDS.64 broadcast
        int rid = half ? p.y : p.x;
        float4 v = __ldg(&tab[rid * 16 + q]);
        acc.x += v.x; acc.y += v.y; acc.z += v.z; acc.w += v.w;
    }
    float4 p4 = make_float4(acc.x * inv_cnt, acc.y * inv_cnt,
                            acc.z * inv_cnt, acc.w * inv_cnt);

    // user + item embeddings
    float4 uv = __ldg(&((const float4*)uW)[user[b] * 32 + lane]);
    int iid  = item[b];
    int rid2 = half ? __ldg(&cate_list[iid]) : iid;
    float4 itv = __ldg(&tab[rid2 * 16 + q]);

    // write tf32-split x
    uint2* xr = &g_xa[b * XD];
    store_split4(xr + lane * 4,       uv);
    store_split4(xr + 128 + lane * 4, itv);
    store_split4(xr + 256 + lane * 4, p4);

    float4* sxr = (float4*)sx[w];
    sxr[lane]      = uv;
    sxr[32 + lane] = itv;
    sxr[64 + lane] = p4;
    __syncthreads();

    // per-CTA reduce over 8 rows, then RED.ADD to global BN accumulators
    for (int f = tid; f < XD; f += 256) {
        float s1 = 0.f, s2 = 0.f;
        #pragma unroll
        for (int r = 0; r < RPB; r++) {
            float v = sx[r][f];
            s1 += v; s2 += v * v;
        }
        atomicAdd(&g_sum[f], s1);
        atomicAdd(&g_sumsq[f], s2);
    }
}

// Self-contained BN fold + weight convert:
//   scale[k] = gamma[k]*rsqrt(var[k]+eps); shift[k] = beta[k]-mean[k]*scale[k]
//   g_w1[n,k] = split(scale[k]*W1[n,k]) (0 for n>=200)
//   g_c[n] = sum_k shift[k]*W1[n,k] + b1[n]
__global__ void convertw_kernel(const float* __restrict__ W1,
                                const float* __restrict__ b1,
                                const float* __restrict__ gamma,
                                const float* __restrict__ beta) {
    __shared__ float red[3];
    int n = blockIdx.x;
    int t = threadIdx.x;         // 0..95
    int k = t * 4;
    const float invN = 1.f / (float)BATCH;

    float4 s4 = *(const float4*)&g_sum[k];
    float4 q4 = *(const float4*)&g_sumsq[k];
    float4 gm = __ldg((const float4*)&gamma[k]);
    float4 bt = __ldg((const float4*)&beta[k]);
    float4 w4 = (n < H1) ? __ldg((const float4*)&W1[n * XD + k])
                         : make_float4(0.f, 0.f, 0.f, 0.f);

    float sv[4] = {s4.x, s4.y, s4.z, s4.w};
    float qv[4] = {q4.x, q4.y, q4.z, q4.w};
    float gv[4] = {gm.x, gm.y, gm.z, gm.w};
    float bv[4] = {bt.x, bt.y, bt.z, bt.w};
    float wv[4] = {w4.x, w4.y, w4.z, w4.w};

    uint2 o[4];
    float part = 0.f;
    #pragma unroll
    for (int j = 0; j < 4; j++) {
        float mean = sv[j] * invN;
        float var  = qv[j] * invN - mean * mean;
        float inv  = rsqrtf(var + BN_EPS);
        float sc   = gv[j] * inv;
        float sf   = bv[j] - mean * sc;
        o[j] = tf32_split(wv[j] * sc);
        part += wv[j] * sf;
    }
    uint2* dst = &g_w1[n * XD + k];
    *(uint4*)(dst)     = make_uint4(o[0].x, o[0].y, o[1].x, o[1].y);
    *(uint4*)(dst + 2) = make_uint4(o[2].x, o[2].y, o[3].x, o[3].y);

    #pragma unroll
    for (int off = 16; off; off >>= 1)
        part += __shfl_down_sync(0xffffffffu, part, off);
    if ((t & 31) == 0) red[t >> 5] = part;
    __syncthreads();
    if (t == 0)
        g_c[n] = red[0] + red[1] + red[2] + ((n < H1) ? __ldg(&b1[n]) : 0.f);
}

// y1 = prelu(x @ (s∘W1)^T + c) via tf32 mma, hi/lo compensated (3 products).
// 3-stage cp.async pipeline (dynamic smem, loads run 2 tiles ahead),
// incremental global pointers. smem [m][k] pitch 20 (conflict-free LDS.64).
// M=4096 N=256 K=384. CTA: BM=64 BN=64 BK=16, 8 warps (4m x 2n), warp 16x32.
// Dead column tiles (>=200) skip mma + B-fragment loads.
#define G1_STG_U2 1280u                 // 64*20 uint2 per stage
#define G1_SMEM   (6 * G1_STG_U2 * 8)   // 3 stages x (A+B) = 61440 B
__global__ void __launch_bounds__(256, 2)
gemm1_kernel(const float* __restrict__ a1p) {
    extern __shared__ uint2 smem_g1[];
    uint2* As = smem_g1;                    // [3][64][20]
    uint2* Bs = smem_g1 + 3 * G1_STG_U2;    // [3][64][20]

    int m0 = blockIdx.x * 64;
    int n0 = blockIdx.y * 64;
    int tid = threadIdx.x;
    int lane = tid & 31, wid = tid >> 5;
    int g = lane >> 2, tig = lane & 3;
    int wm = wid & 3;    // 4 m-warps: 16 rows each
    int wn = wid >> 2;   // 2 n-warps: 32 cols each

    // loader: row lm 0..63, k-quad kq (2 x 16B per tile per matrix)
    int lm = tid >> 2;
    int kq = (tid & 3) * 4;
    const uint2* pa = g_xa + (m0 + lm) * XD + kq;
    const uint2* pb = g_w1 + (n0 + lm) * XD + kq;
    uint32_t sA = (uint32_t)__cvta_generic_to_shared(As) + (lm * 20 + kq) * 8;
    uint32_t sB = (uint32_t)__cvta_generic_to_shared(Bs) + (lm * 20 + kq) * 8;
    const uint32_t STG = G1_STG_U2 * 8;     // 10240 B

    bool ntv[4];
    #pragma unroll
    for (int nt = 0; nt < 4; nt++) ntv[nt] = (n0 + wn * 32 + nt * 8) < H1;

    float4 acc[4];
    #pragma unroll
    for (int nt = 0; nt < 4; nt++) acc[nt] = make_float4(0.f, 0.f, 0.f, 0.f);

    // prologue: tiles 0 and 1 into stages 0,1
    cp16(sA,            pa); cp16(sA + 16,       pa + 2);
    cp16(sB,            pb); cp16(sB + 16,       pb + 2);
    cp_commit();
    pa += 16; pb += 16;
    cp16(sA + STG,      pa); cp16(sA + STG + 16, pa + 2);
    cp16(sB + STG,      pb); cp16(sB + STG + 16, pb + 2);
    cp_commit();
    pa += 16; pb += 16;

    // fragment row offsets (uint2 units)
    int raf = (wm * 16 + g) * 20;
    int rbf = (wn * 32 + g) * 20;

    #pragma unroll 1
    for (int it = 0; it < 24; it++) {
        if (it < 23) cp_wait1(); else cp_wait0();
        __syncthreads();
        if (it < 22) {
            uint32_t off = (uint32_t)((it + 2) % 3) * STG;
            cp16(sA + off,      pa); cp16(sA + off + 16, pa + 2);
            cp16(sB + off,      pb); cp16(sB + off + 16, pb + 2);
            cp_commit();
            pa += 16; pb += 16;
        }

        const uint2* ab = As + (it % 3) * G1_STG_U2;
        const uint2* bb = Bs + (it % 3) * G1_STG_U2;
        #pragma unroll
        for (int ks = 0; ks < 2; ks++) {
            int kb = ks * 8;
            uint2 a0 = ab[raf + kb + tig];
            uint2 a1 = ab[raf + 8 * 20 + kb + tig];
            uint2 a2 = ab[raf + kb + tig + 4];
            uint2 a3 = ab[raf + 8 * 20 + kb + tig + 4];
            #pragma unroll
            for (int nt = 0; nt < 4; nt++) {
                if (ntv[nt]) {
                    uint2 b0 = bb[rbf + nt * 8 * 20 + kb + tig];
                    uint2 b1 = bb[rbf + nt * 8 * 20 + kb + tig + 4];
                    mma_tf32(acc[nt], a0.x, a1.x, a2.x, a3.x, b0.x, b1.x);
                    mma_tf32(acc[nt], a0.x, a1.x, a2.x, a3.x, b0.y, b1.y);
                    mma_tf32(acc[nt], a0.y, a1.y, a2.y, a3.y, b0.x, b1.x);
                }
            }
        }
    }

    // epilogue: + g_c (bias + BN shift folded), prelu, write y1
    float alpha = __ldg(a1p);
    int row = m0 + wm * 16 + g;
    #pragma unroll
    for (int nt = 0; nt < 4; nt++) {
        int col = n0 + wn * 32 + nt * 8 + tig * 2;
        if (col < H1) {
            float c0 = g_c[col], c1 = g_c[col + 1];
            float v0 = acc[nt].x + c0;
            float v1 = acc[nt].y + c1;
            float v2 = acc[nt].z + c0;
            float v3 = acc[nt].w + c1;
            v0 = (v0 >= 0.f) ? v0 : alpha * v0;
            v1 = (v1 >= 0.f) ? v1 : alpha * v1;
            v2 = (v2 >= 0.f) ? v2 : alpha * v2;
            v3 = (v3 >= 0.f) ? v3 : alpha * v3;
            *(float2*)&g_y1[row * H1 + col]       = make_float2(v0, v1);
            *(float2*)&g_y1[(row + 8) * H1 + col] = make_float2(v2, v3);
        }
    }
}

// y2 = prelu(y1 @ W2^T + b2); logits = y2 @ W3^T + b3; softmax — fused.
// Block 0 also resets BN accumulators for the next graph replay.
// M=4096 N=80 K=200; BM=64 BN=80 BK=8, 256 threads, 4x5, double-buffered.
__global__ void gemm2_out_kernel(const float* __restrict__ W2,
                                 const float* __restrict__ b2,
                                 const float* __restrict__ a2p,
                                 const float* __restrict__ W3,
                                 const float* __restrict__ b3,
                                 float* __restrict__ out) {
    __shared__ float As[2][8][68];
    __shared__ float Bs[2][8][84];
    __shared__ float sy[64][81];
    __shared__ float sw3[2 * H2];

    int m0 = blockIdx.x * 64;
    int tid = threadIdx.x;

    // next-replay resets (safe: convertw consumed these before gemm1/gemm2 run)
    if (blockIdx.x == 0) {
        if (tid < 256) { g_sum[tid] = 0.f; g_sumsq[tid] = 0.f; }
        if (tid < XD - 256) { g_sum[256 + tid] = 0.f; g_sumsq[256 + tid] = 0.f; }
        if (tid == 0) g_first_inactive = BATCH;
    }

    int tx = tid & 15, ty = tid >> 4;     // tx -> n (5 each), ty -> m (4 each)
    int lk2 = (tid & 3) * 2, lm = tid >> 2;       // A loader: float2 along k
    int bn = tid >> 1, bq = (tid & 1) * 4;        // B loader: threads<160 load float4

    if (tid < 2 * H2) sw3[tid] = W3[tid];

    float acc[4][5];
    #pragma unroll
    for (int i = 0; i < 4; i++)
        #pragma unroll
        for (int j = 0; j < 5; j++) acc[i][j] = 0.f;

    // prologue
    float2 pa = *(const float2*)&g_y1[(m0 + lm) * H1 + lk2];
    float4 pb = (tid < 160) ? *(const float4*)&W2[bn * H1 + bq]
                            : make_float4(0.f, 0.f, 0.f, 0.f);
    As[0][lk2 + 0][lm] = pa.x;
    As[0][lk2 + 1][lm] = pa.y;
    if (tid < 160) {
        Bs[0][bq + 0][bn] = pb.x; Bs[0][bq + 1][bn] = pb.y;
        Bs[0][bq + 2][bn] = pb.z; Bs[0][bq + 3][bn] = pb.w;
    }
    __syncthreads();

    #pragma unroll 1
    for (int it = 0; it < 25; it++) {
        int cur = it & 1;
        float2 na; float4 nb;
        int k0n = (it + 1) * 8;
        if (it < 24) {
            na = *(const float2*)&g_y1[(m0 + lm) * H1 + k0n + lk2];
            if (tid < 160) nb = *(const float4*)&W2[bn * H1 + k0n + bq];
        }
        #pragma unroll
        for (int kk = 0; kk < 8; kk++) {
            float4 ta = *(const float4*)&As[cur][kk][ty * 4];
            float a[4] = {ta.x, ta.y, ta.z, ta.w};
            float bb[5];
            #pragma unroll
            for (int j = 0; j < 5; j++) bb[j] = Bs[cur][kk][tx * 5 + j];
            #pragma unroll
            for (int i = 0; i < 4; i++)
                #pragma unroll
                for (int j = 0; j < 5; j++) acc[i][j] += a[i] * bb[j];
        }
        if (it < 24) {
            int nxt = cur ^ 1;
            As[nxt][lk2 + 0][lm] = na.x;
            As[nxt][lk2 + 1][lm] = na.y;
            if (tid < 160) {
                Bs[nxt][bq + 0][bn] = nb.x; Bs[nxt][bq + 1][bn] = nb.y;
                Bs[nxt][bq + 2][bn] = nb.z; Bs[nxt][bq + 3][bn] = nb.w;
            }
        }
        __syncthreads();
    }

    float alpha = a2p[0];
    #pragma unroll
    for (int i = 0; i < 4; i++)
        #pragma unroll
        for (int j = 0; j < 5; j++) {
            float v = acc[i][j] + b2[tx * 5 + j];
            v = (v >= 0.f) ? v : alpha * v;
            sy[ty * 4 + i][tx * 5 + j] = v;
        }
    __syncthreads();

    // logits + softmax: 4 threads per row, 20 dims each, shuffle-combine
    int row = tid >> 2, part = tid & 3;
    float s0 = 0.f, s1 = 0.f;
    int kbase = part * 20;
    #pragma unroll
    for (int k = 0; k < 20; k++) {
        float v = sy[row][kbase + k];
        s0 += v * sw3[kbase + k];
        s1 += v * sw3[H2 + kbase + k];
    }
    s0 += __shfl_down_sync(0xffffffffu, s0, 2, 4);
    s0 += __shfl_down_sync(0xffffffffu, s0, 1, 4);
    s1 += __shfl_down_sync(0xffffffffu, s1, 2, 4);
    s1 += __shfl_down_sync(0xffffffffu, s1, 1, 4);
    if (part == 0) {
        float l0 = s0 + b3[0], l1 = s1 + b3[1];
        float m = fmaxf(l0, l1);
        float e0 = expf(l0 - m), e1 = expf(l1 - m);
        float inv = 1.f / (e0 + e1);
        out[(m0 + row) * 2 + 0] = e0 * inv;
        out[(m0 + row) * 2 + 1] = e1 * inv;
    }
}

// ---------------- launch ----------------
extern "C" void kernel_launch(void* const* d_in, const int* in_sizes, int n_in,
                              void* d_out, int out_size) {
    const int*   user      = (const int*)d_in[0];
    const int*   item      = (const int*)d_in[1];
    const int*   history   = (const int*)d_in[2];
    // d_in[3] = length (unused; semantics derived from history zeros)
    const int*   cate_list = (const int*)d_in[4];
    const float* uW        = (const float*)d_in[5];
    const float* iW        = (const float*)d_in[6];
    const float* cW        = (const float*)d_in[7];
    const float* gamma     = (const float*)d_in[8];
    const float* beta      = (const float*)d_in[9];
    const float* W1        = (const float*)d_in[10];
    const float* b1        = (const float*)d_in[11];
    const float* a1        = (const float*)d_in[12];
    const float* W2        = (const float*)d_in[13];
    const float* b2        = (const float*)d_in[14];
    const float* a2        = (const float*)d_in[15];
    const float* W3        = (const float*)d_in[16];
    const float* b3        = (const float*)d_in[17];
    float* out = (float*)d_out;

    cudaFuncSetAttribute(gemm1_kernel,
                         cudaFuncAttributeMaxDynamicSharedMemorySize, G1_SMEM);

    scan_kernel<<<16, 256>>>(history);
    embed_kernel<<<BATCH / RPB, 256>>>(user, item, history, cate_list, uW, iW, cW);
    convertw_kernel<<<N1P, 96>>>(W1, b1, gamma, beta);
    dim3 g1(BATCH / 64, 4);
    gemm1_kernel<<<g1, 256, G1_SMEM>>>(a1);
    gemm2_out_kernel<<<BATCH / 64, 256>>>(W2, b2, a2, W3, b3, out);
}